// round 14
// baseline (speedup 1.0000x reference)
#include <cuda_runtime.h>

// Quanvolution, 2 patches per thread, f32x2 lanes = (patchA, patchB).
// R14: persistent single-wave grid (784 CTAs x 4 tiles/thread, exact cover;
// launch_bounds(256,6) pins <=42 regs so 6 CTAs/SM => capacity 888 >= 784)
// with ZERO-REGISTER prefetch: prefetch.global.L1 of tile t+1 issued before
// computing tile t (no destination reg, no smem, no barriers). Tile stride
// 200704 floats = 98*2048 => batch += 2048/tile, (pp,pr,pj) invariant.
// Compute body identical to R8: tan-form unnormalized RY butterflies (2 fma2,
// UR constants -> rt=2), K=prod-cos folded into Q, Gray-folded CNOT chains,
// MUFU encoding trig. Setup kernel writes the __constant__ backing store.

#define NB    8192
#define PPB2  98
#define NTH   (NB * PPB2)            // 802,816
#define TPB   256
#define NBLK  784                    // 784*256*4 == NTH exactly
#define TSTRIDE 1605632              // floats per tile step: 2048 batches * 784

typedef unsigned long long u64;

// c_k[0..7]  = (+tan(par[k]/2)) dup'd f32x2
// c_k[8..15] = (-tan(par[k]/2)) dup'd f32x2
// c_k[16]    = (prod_k cos(par[k]/2)) dup'd f32x2
__constant__ u64 c_k[17];

static __device__ __forceinline__ u64 pk2(float lo, float hi) {
    u64 r; asm("mov.b64 %0, {%1, %2};" : "=l"(r) : "f"(lo), "f"(hi)); return r;
}
static __device__ __forceinline__ void upk2(u64 v, float& lo, float& hi) {
    asm("mov.b64 {%0, %1}, %2;" : "=f"(lo), "=f"(hi) : "l"(v));
}
static __device__ __forceinline__ u64 fma2(u64 a, u64 b, u64 c) {
    u64 d; asm("fma.rn.f32x2 %0, %1, %2, %3;" : "=l"(d) : "l"(a), "l"(b), "l"(c)); return d;
}
static __device__ __forceinline__ u64 mul2(u64 a, u64 b) {
    u64 d; asm("mul.rn.f32x2 %0, %1, %2;" : "=l"(d) : "l"(a), "l"(b)); return d;
}
static __device__ __forceinline__ u64 add2(u64 a, u64 b) {
    u64 d; asm("add.rn.f32x2 %0, %1, %2;" : "=l"(d) : "l"(a), "l"(b)); return d;
}
static __device__ __forceinline__ u64 sub2(u64 a, u64 b) {
    u64 d; asm("sub.rn.f32x2 %0, %1, %2;" : "=l"(d) : "l"(a), "l"(b)); return d;
}

static __device__ __forceinline__ void bf_tan(u64& lo, u64& hi, u64 pt, u64 nt) {
    u64 l1 = fma2(nt, hi, lo);
    hi     = fma2(pt, lo, hi);
    lo     = l1;
}

template<int BIT>
static __device__ __forceinline__ void ry_wire(u64 (&v)[16], u64 pt, u64 nt) {
    #pragma unroll
    for (int i = 0; i < 16; ++i)
        if (!(i & BIT))
            bf_tan(v[i], v[i | BIT], pt, nt);
}

static __device__ __forceinline__ void gray_perm(u64 (&v)[16]) {
    u64 t[16];
    #pragma unroll
    for (int i = 0; i < 16; ++i) t[i] = v[i ^ (i >> 1)];
    #pragma unroll
    for (int i = 0; i < 16; ++i) v[i] = t[i];
}

__global__ void setup_kernel(const float* __restrict__ par, u64* __restrict__ dst) {
    int lane = threadIdx.x;
    int k = lane & 7;
    float h = 0.5f * par[k];
    float s = sinf(h);
    float c = cosf(h);
    float t = s / c;
    float kp = c;
    kp *= __shfl_xor_sync(0xFFFFFFFFu, kp, 1);
    kp *= __shfl_xor_sync(0xFFFFFFFFu, kp, 2);
    kp *= __shfl_xor_sync(0xFFFFFFFFu, kp, 4);
    if (lane < 8) {
        dst[k]     = ((u64)__float_as_uint( t)) | ((u64)__float_as_uint( t) << 32);
        dst[8 + k] = ((u64)__float_as_uint(-t)) | ((u64)__float_as_uint(-t) << 32);
        if (lane == 0)
            dst[16] = ((u64)__float_as_uint(kp)) | ((u64)__float_as_uint(kp) << 32);
    }
}

// one (batch, patch-pair) tile: r0 = img row 2pr (A0 A1 B0 B1),
// r1 = img row 2pr+1 (A2 A3 B2 B3); writes 8 floats at op.
static __device__ __forceinline__ void compute_tile(float4 r0, float4 r1,
                                                    float* __restrict__ op)
{
    float h;
    h = 0.5f * r0.x; float cA0 = __cosf(h), sA0 = __sinf(h);
    h = 0.5f * r0.y; float cA1 = __cosf(h), sA1 = __sinf(h);
    h = 0.5f * r1.x; float cA2 = __cosf(h), sA2 = __sinf(h);
    h = 0.5f * r1.y; float cA3 = __cosf(h), sA3 = __sinf(h);
    h = 0.5f * r0.z; float cB0 = __cosf(h), sB0 = __sinf(h);
    h = 0.5f * r0.w; float cB1 = __cosf(h), sB1 = __sinf(h);
    h = 0.5f * r1.z; float cB2 = __cosf(h), sB2 = __sinf(h);
    h = 0.5f * r1.w; float cB3 = __cosf(h), sB3 = __sinf(h);

    u64 c0 = pk2(cA0, cB0), s0 = pk2(sA0, sB0);
    u64 c1 = pk2(cA1, cB1), s1 = pk2(sA1, sB1);
    u64 c2 = pk2(cA2, cB2), s2 = pk2(sA2, sB2);
    u64 c3 = pk2(cA3, cB3), s3 = pk2(sA3, sB3);

    // v[i] = P01[i0*2+i1] * Q[(i2^i1)*2 + (i3^i2)]  (first CNOT chain folded)
    u64 P01[4];
    P01[0] = mul2(c0, c1);
    P01[1] = mul2(c0, s1);
    P01[2] = mul2(s0, s1);
    P01[3] = mul2(s0, c1);

    // layer-1 wire-0 RY folded into P
    bf_tan(P01[0], P01[2], c_k[0], c_k[8]);
    bf_tan(P01[1], P01[3], c_k[0], c_k[8]);

    // normalization K = prod cos(par/2) folded into Q
    u64 Kc  = c_k[16];
    u64 c2K = mul2(c2, Kc);
    u64 s2K = mul2(s2, Kc);
    u64 Q[4];
    Q[0] = mul2(c2K, c3);
    Q[1] = mul2(c2K, s3);
    Q[2] = mul2(s2K, c3);
    Q[3] = mul2(s2K, s3);

    u64 v[16];
    #pragma unroll
    for (int i = 0; i < 16; ++i) {
        int i0 = (i >> 3) & 1, i1 = (i >> 2) & 1, i2 = (i >> 1) & 1, i3 = i & 1;
        v[i] = mul2(P01[i0 * 2 + i1], Q[(i2 ^ i1) * 2 + (i3 ^ i2)]);
    }

    ry_wire<4>(v, c_k[1], c_k[9]);
    ry_wire<2>(v, c_k[2], c_k[10]);
    ry_wire<1>(v, c_k[3], c_k[11]);
    gray_perm(v);
    ry_wire<8>(v, c_k[4], c_k[12]);
    ry_wire<4>(v, c_k[5], c_k[13]);
    ry_wire<2>(v, c_k[6], c_k[14]);
    ry_wire<1>(v, c_k[7], c_k[15]);
    // final CNOT chain folded into measurement signs (prefix parities)

    u64 p[16];
    #pragma unroll
    for (int i = 0; i < 16; ++i) p[i] = mul2(v[i], v[i]);

    u64 sa[8], da[8];
    #pragma unroll
    for (int k = 0; k < 8; ++k) {
        sa[k] = add2(p[2 * k], p[2 * k + 1]);
        da[k] = sub2(p[2 * k], p[2 * k + 1]);
    }
    u64 z3 = sub2(sub2(sub2(da[0], da[1]), sub2(da[2], da[3])),
                  sub2(sub2(da[4], da[5]), sub2(da[6], da[7])));

    u64 sb[4], e[4];
    #pragma unroll
    for (int j = 0; j < 4; ++j) {
        sb[j] = add2(sa[2 * j], sa[2 * j + 1]);
        e[j]  = sub2(sa[2 * j], sa[2 * j + 1]);
    }
    u64 z2 = sub2(sub2(e[0], e[1]), sub2(e[2], e[3]));

    u64 U0 = add2(sb[0], sb[1]), U1 = add2(sb[2], sb[3]);
    u64 E0 = sub2(sb[0], sb[1]), E1 = sub2(sb[2], sb[3]);
    u64 z1 = sub2(E0, E1);
    u64 z0 = sub2(U0, U1);

    float za0, zb0, za1, zb1, za2, zb2, za3, zb3;
    upk2(z0, za0, zb0); upk2(z1, za1, zb1);
    upk2(z2, za2, zb2); upk2(z3, za3, zb3);

    float4* o = reinterpret_cast<float4*>(op);
    o[0] = make_float4(za0, za1, za2, za3);
    o[1] = make_float4(zb0, zb1, zb2, zb3);
}

__global__ void __launch_bounds__(TPB, 6)
quanv_kernel(const float* __restrict__ x, float* __restrict__ out)
{
    int tid = threadIdx.x;
    int gid = blockIdx.x * TPB + tid;   // tile-0 id; tiles: gid + t*200704
    int b0  = gid / PPB2;               // 0..2047
    int pp  = gid - b0 * PPB2;
    int pr  = pp / 7;
    int pj  = pp - pr * 7;
    // 200704 = 98*2048: per tile, batch += 2048; (pp,pr,pj) invariant.

    const float* ip = x   + b0 * 784 + pr * 56 + pj * 4;
    float*       op = out + b0 * 784 + pr * 56 + pj * 8;

    #pragma unroll
    for (int t = 0; t < 4; ++t) {
        if (t < 3) {
            // zero-register prefetch of the next tile's two 16B lines
            asm volatile("prefetch.global.L1 [%0];" :: "l"(ip + (t + 1) * TSTRIDE));
            asm volatile("prefetch.global.L1 [%0];" :: "l"(ip + (t + 1) * TSTRIDE + 28));
        }
        float4 r0 = *reinterpret_cast<const float4*>(ip + t * TSTRIDE);
        float4 r1 = *reinterpret_cast<const float4*>(ip + t * TSTRIDE + 28);
        compute_tile(r0, r1, op + t * TSTRIDE);
    }
}

extern "C" void kernel_launch(void* const* d_in, const int* in_sizes, int n_in,
                              void* d_out, int out_size)
{
    const float* x   = (const float*)d_in[0];   // (8192,1,28,28) fp32
    const float* par = (const float*)d_in[1];   // (2,4) fp32
    float* out       = (float*)d_out;           // (8192, 784) fp32
    (void)in_sizes; (void)n_in; (void)out_size;

    void* ck_addr = nullptr;
    cudaGetSymbolAddress(&ck_addr, c_k);        // address query only — no alloc

    setup_kernel<<<1, 32>>>(par, (u64*)ck_addr);
    quanv_kernel<<<NBLK, TPB>>>(x, out);
}

// round 15
// speedup vs baseline: 1.1024x; 1.1024x over previous
#include <cuda_runtime.h>

// Quanvolution, 2 patches per thread, f32x2 lanes = (patchA, patchB).
// R15: R8 architecture (simple oversubscribed grid — beats all persistent
// variants) with TPB 128 / launch_bounds(128,12): same 48-warp occupancy
// ceiling at regs<=42, but half-size scheduling quanta cut wave-tail bubbles.
// Body identical to R8: tan-form unnormalized RY butterflies (2 fma2 each,
// __constant__ -> uniform-reg gate tangents, rt=2), K=prod-cos folded into
// the Q encoding factor, first/last CNOT chains folded into encoding build /
// measurement sign patterns, middle chain = Gray register rename, MUFU trig.

#define NB    8192
#define PPB2  98                    // patch PAIRS per batch (196/2)
#define NTH   (NB * PPB2)           // 802,816 = 6272 * 128
#define TPB   128

typedef unsigned long long u64;

// c_k[0..7]  = (+tan(par[k]/2)) dup'd f32x2
// c_k[8..15] = (-tan(par[k]/2)) dup'd f32x2
// c_k[16]    = (prod_k cos(par[k]/2)) dup'd f32x2
__constant__ u64 c_k[17];

static __device__ __forceinline__ u64 pk2(float lo, float hi) {
    u64 r; asm("mov.b64 %0, {%1, %2};" : "=l"(r) : "f"(lo), "f"(hi)); return r;
}
static __device__ __forceinline__ void upk2(u64 v, float& lo, float& hi) {
    asm("mov.b64 {%0, %1}, %2;" : "=f"(lo), "=f"(hi) : "l"(v));
}
static __device__ __forceinline__ u64 fma2(u64 a, u64 b, u64 c) {
    u64 d; asm("fma.rn.f32x2 %0, %1, %2, %3;" : "=l"(d) : "l"(a), "l"(b), "l"(c)); return d;
}
static __device__ __forceinline__ u64 mul2(u64 a, u64 b) {
    u64 d; asm("mul.rn.f32x2 %0, %1, %2;" : "=l"(d) : "l"(a), "l"(b)); return d;
}
static __device__ __forceinline__ u64 add2(u64 a, u64 b) {
    u64 d; asm("add.rn.f32x2 %0, %1, %2;" : "=l"(d) : "l"(a), "l"(b)); return d;
}
static __device__ __forceinline__ u64 sub2(u64 a, u64 b) {
    u64 d; asm("sub.rn.f32x2 %0, %1, %2;" : "=l"(d) : "l"(a), "l"(b)); return d;
}

// unnormalized tan-form RY butterfly: lo' = lo - t*hi ; hi' = t*lo + hi
static __device__ __forceinline__ void bf_tan(u64& lo, u64& hi, u64 pt, u64 nt) {
    u64 l1 = fma2(nt, hi, lo);
    hi     = fma2(pt, lo, hi);
    lo     = l1;
}

template<int BIT>
static __device__ __forceinline__ void ry_wire(u64 (&v)[16], u64 pt, u64 nt) {
    #pragma unroll
    for (int i = 0; i < 16; ++i)
        if (!(i & BIT))
            bf_tan(v[i], v[i | BIT], pt, nt);
}

// CNOT chain (0,1)(1,2)(2,3): new[i] = old[i ^ (i>>1)] — register rename only.
static __device__ __forceinline__ void gray_perm(u64 (&v)[16]) {
    u64 t[16];
    #pragma unroll
    for (int i = 0; i < 16; ++i) t[i] = v[i ^ (i >> 1)];
    #pragma unroll
    for (int i = 0; i < 16; ++i) v[i] = t[i];
}

__global__ void setup_kernel(const float* __restrict__ par, u64* __restrict__ dst) {
    int lane = threadIdx.x;
    int k = lane & 7;
    float h = 0.5f * par[k];
    float s = sinf(h);
    float c = cosf(h);
    float t = s / c;
    float kp = c;
    kp *= __shfl_xor_sync(0xFFFFFFFFu, kp, 1);
    kp *= __shfl_xor_sync(0xFFFFFFFFu, kp, 2);
    kp *= __shfl_xor_sync(0xFFFFFFFFu, kp, 4);
    if (lane < 8) {
        dst[k]     = ((u64)__float_as_uint( t)) | ((u64)__float_as_uint( t) << 32);
        dst[8 + k] = ((u64)__float_as_uint(-t)) | ((u64)__float_as_uint(-t) << 32);
        if (lane == 0)
            dst[16] = ((u64)__float_as_uint(kp)) | ((u64)__float_as_uint(kp) << 32);
    }
}

__global__ void __launch_bounds__(TPB, 12)
quanv_kernel(const float* __restrict__ x, float* __restrict__ out)
{
    int gid = blockIdx.x * TPB + threadIdx.x;    // NTH == gridDim*TPB exactly
    int b   = gid / PPB2;
    int pp  = gid - b * PPB2;                    // patch-pair index 0..97
    int pr  = pp / 7;                            // patch row 0..13
    int pj  = pp - pr * 7;                       // pair-column 0..6

    // two adjacent 2x2 patches = 2 coalesced float4 loads
    const float4* src = reinterpret_cast<const float4*>(x + b * 784 + pr * 56 + pj * 4);
    float4 r0 = src[0];   // row 2pr  : A0 A1 B0 B1
    float4 r1 = src[7];   // row 2pr+1: A2 A3 B2 B3

    // encoding trig on MUFU pipe (lanes = patches)
    float h;
    h = 0.5f * r0.x; float cA0 = __cosf(h), sA0 = __sinf(h);
    h = 0.5f * r0.y; float cA1 = __cosf(h), sA1 = __sinf(h);
    h = 0.5f * r1.x; float cA2 = __cosf(h), sA2 = __sinf(h);
    h = 0.5f * r1.y; float cA3 = __cosf(h), sA3 = __sinf(h);
    h = 0.5f * r0.z; float cB0 = __cosf(h), sB0 = __sinf(h);
    h = 0.5f * r0.w; float cB1 = __cosf(h), sB1 = __sinf(h);
    h = 0.5f * r1.z; float cB2 = __cosf(h), sB2 = __sinf(h);
    h = 0.5f * r1.w; float cB3 = __cosf(h), sB3 = __sinf(h);

    u64 c0 = pk2(cA0, cB0), s0 = pk2(sA0, sB0);
    u64 c1 = pk2(cA1, cB1), s1 = pk2(sA1, sB1);
    u64 c2 = pk2(cA2, cB2), s2 = pk2(sA2, sB2);
    u64 c3 = pk2(cA3, cB3), s3 = pk2(sA3, sB3);

    // separable encoding with the FIRST CNOT chain pre-folded:
    // v[i] = P01[i0*2+i1] * Q[(i2^i1)*2 + (i3^i2)], P01[i0*2+i1] = g0[i0]*g1[i1^i0]
    u64 P01[4];
    P01[0] = mul2(c0, c1);
    P01[1] = mul2(c0, s1);
    P01[2] = mul2(s0, s1);
    P01[3] = mul2(s0, c1);

    // layer-1 wire-0 RY folded into P (butterfly pairs share the Q factor)
    bf_tan(P01[0], P01[2], c_k[0], c_k[8]);
    bf_tan(P01[1], P01[3], c_k[0], c_k[8]);

    // normalization K = prod cos(par/2) folded into the Q factor
    u64 Kc  = c_k[16];
    u64 c2K = mul2(c2, Kc);
    u64 s2K = mul2(s2, Kc);
    u64 Q[4];                        // [x*2+y] = (K*g2[x])*g3[y]
    Q[0] = mul2(c2K, c3);
    Q[1] = mul2(c2K, s3);
    Q[2] = mul2(s2K, c3);
    Q[3] = mul2(s2K, s3);

    u64 v[16];
    #pragma unroll
    for (int i = 0; i < 16; ++i) {
        int i0 = (i >> 3) & 1, i1 = (i >> 2) & 1, i2 = (i >> 1) & 1, i3 = i & 1;
        v[i] = mul2(P01[i0 * 2 + i1], Q[(i2 ^ i1) * 2 + (i3 ^ i2)]);
    }

    // rest of variational layer 1 (wire 0 already applied)
    ry_wire<4>(v, c_k[1], c_k[9]);
    ry_wire<2>(v, c_k[2], c_k[10]);
    ry_wire<1>(v, c_k[3], c_k[11]);
    gray_perm(v);                    // middle CNOT chain: free rename
    // variational layer 2
    ry_wire<8>(v, c_k[4], c_k[12]);
    ry_wire<4>(v, c_k[5], c_k[13]);
    ry_wire<2>(v, c_k[6], c_k[14]);
    ry_wire<1>(v, c_k[7], c_k[15]);
    // final CNOT chain folded into measurement signs (prefix parities)

    u64 p[16];
    #pragma unroll
    for (int i = 0; i < 16; ++i) p[i] = mul2(v[i], v[i]);

    u64 sa[8], da[8];
    #pragma unroll
    for (int k = 0; k < 8; ++k) {
        sa[k] = add2(p[2 * k], p[2 * k + 1]);
        da[k] = sub2(p[2 * k], p[2 * k + 1]);
    }
    u64 z3 = sub2(sub2(sub2(da[0], da[1]), sub2(da[2], da[3])),
                  sub2(sub2(da[4], da[5]), sub2(da[6], da[7])));

    u64 sb[4], e[4];
    #pragma unroll
    for (int j = 0; j < 4; ++j) {
        sb[j] = add2(sa[2 * j], sa[2 * j + 1]);
        e[j]  = sub2(sa[2 * j], sa[2 * j + 1]);
    }
    u64 z2 = sub2(sub2(e[0], e[1]), sub2(e[2], e[3]));

    u64 U0 = add2(sb[0], sb[1]), U1 = add2(sb[2], sb[3]);
    u64 E0 = sub2(sb[0], sb[1]), E1 = sub2(sb[2], sb[3]);
    u64 z1 = sub2(E0, E1);
    u64 z0 = sub2(U0, U1);

    float za0, zb0, za1, zb1, za2, zb2, za3, zb3;
    upk2(z0, za0, zb0); upk2(z1, za1, zb1);
    upk2(z2, za2, zb2); upk2(z3, za3, zb3);

    float4* o = reinterpret_cast<float4*>(out + ((size_t)b * 784 + pr * 56 + pj * 8));
    o[0] = make_float4(za0, za1, za2, za3);
    o[1] = make_float4(zb0, zb1, zb2, zb3);
}

extern "C" void kernel_launch(void* const* d_in, const int* in_sizes, int n_in,
                              void* d_out, int out_size)
{
    const float* x   = (const float*)d_in[0];   // (8192,1,28,28) fp32
    const float* par = (const float*)d_in[1];   // (2,4) fp32
    float* out       = (float*)d_out;           // (8192, 784) fp32
    (void)in_sizes; (void)n_in; (void)out_size;

    void* ck_addr = nullptr;
    cudaGetSymbolAddress(&ck_addr, c_k);        // address query only — no alloc

    setup_kernel<<<1, 32>>>(par, (u64*)ck_addr);
    quanv_kernel<<<NTH / TPB, TPB>>>(x, out);
}